// round 13
// baseline (speedup 1.0000x reference)
#include <cuda_runtime.h>
#include <cuda_bf16.h>
#include <cstdint>

// ============================================================================
// Problem constants
// ============================================================================
#define BB       512
#define TT       100          // K per batch
#define TPAD     112          // padded to 7 x k16
#define NPRE     256
#define NPOST    256
#define KTOT     (BB * TT)    // 51200
#define KSPLIT   74           // grid (74, 2 mtiles) = 148 CTAs = one wave

// A tile (trace bf16, [p][t]): 128 rows, stride 240B (16B-mult, conflict-free)
#define A_ROW_B   240
#define A_TILE_B  (128 * A_ROW_B)       // 30720
// B tile (post bf16, [t][q]): 112 rows x 256 bf16, stride 528B (double-buffered)
#define B_ROW_B   528
#define B_TILE_B  (TPAD * B_ROW_B)      // 59136
// pre staging (fp32, [t][p]): 104 rows (4 zeroed slack) x 132 f32
#define STG_ROW_B 528
#define STG_ROW_F 132
#define STG_B     (104 * STG_ROW_B)     // 54912

#define SM_A      0
#define SM_B0     A_TILE_B                       // 30720
#define SM_B1     (A_TILE_B + B_TILE_B)          // 89856
#define SM_STG    (A_TILE_B + 2 * B_TILE_B)      // 148992
#define GEMM_SMEM (SM_STG + STG_B)               // 203904

// ============================================================================
// PTX helpers (baseline PTX only — tcgen05 unavailable on plain sm_103 target)
// ============================================================================
__device__ __forceinline__ void ldmatrix_x4(uint32_t* r, uint32_t addr) {
    asm volatile("ldmatrix.sync.aligned.m8n8.x4.shared.b16 {%0,%1,%2,%3}, [%4];"
                 : "=r"(r[0]), "=r"(r[1]), "=r"(r[2]), "=r"(r[3]) : "r"(addr));
}
__device__ __forceinline__ void ldmatrix_x4_trans(uint32_t* r, uint32_t addr) {
    asm volatile("ldmatrix.sync.aligned.m8n8.x4.trans.shared.b16 {%0,%1,%2,%3}, [%4];"
                 : "=r"(r[0]), "=r"(r[1]), "=r"(r[2]), "=r"(r[3]) : "r"(addr));
}
__device__ __forceinline__ void mma_16816(float* c, const uint32_t* a, const uint32_t* b) {
    asm volatile(
        "mma.sync.aligned.m16n8k16.row.col.f32.bf16.bf16.f32 "
        "{%0,%1,%2,%3}, {%4,%5,%6,%7}, {%8,%9}, {%0,%1,%2,%3};"
        : "+f"(c[0]), "+f"(c[1]), "+f"(c[2]), "+f"(c[3])
        : "r"(a[0]), "r"(a[1]), "r"(a[2]), "r"(a[3]), "r"(b[0]), "r"(b[1]));
}
__device__ __forceinline__ uint32_t smem_to_u32(const void* smem_ptr) {
    uint32_t addr;
    asm("{ .reg .u64 tmp; cvta.to.shared.u64 tmp, %1; cvt.u32.u64 %0, tmp; }"
        : "=r"(addr) : "l"(smem_ptr));
    return addr;
}
__device__ __forceinline__ void cp_async_16(uint32_t dst_smem, const void* src) {
    asm volatile("cp.async.cg.shared.global [%0], [%1], 16;"
                 :: "r"(dst_smem), "l"(src) : "memory");
}
#define CP_ASYNC_COMMIT() asm volatile("cp.async.commit_group;" ::: "memory")
#define CP_ASYNC_WAIT0()  asm volatile("cp.async.wait_group 0;" ::: "memory")

__device__ __forceinline__ uint32_t pack_bf16x2(float a, float b) {
    return ((uint32_t)__bfloat16_as_ushort(__float2bfloat16(b)) << 16)
         |  (uint32_t)__bfloat16_as_ushort(__float2bfloat16(a));
}

// ============================================================================
// Kernel 0: zero the output (d_out is poisoned; atomics need a clean base)
// ============================================================================
__global__ void stdp_zero_kernel(float4* __restrict__ out) {
    out[blockIdx.x * blockDim.x + threadIdx.x] = make_float4(0.f, 0.f, 0.f, 0.f);
}

// ============================================================================
// Fused kernel: pipelined post-convert hidden inside the MMA phase (B double-
//   buffered) + cp.async pre staging + shuffle-carry scan (only exposed work).
//   grid (74, mtile 2) = 148 CTAs, 512 threads = 16 warps (2 M x 8 N)
// ============================================================================
__global__ void __launch_bounds__(512, 1) stdp_fused_kernel(
    const float* __restrict__ pre, const float* __restrict__ post,
    float* __restrict__ out)
{
    extern __shared__ __align__(16) char smem[];
    const uint32_t su = smem_to_u32(smem);
    float* stg = (float*)(smem + SM_STG);      // [104][132] fp32 pre staging

    const int tid    = threadIdx.x;
    const int wid    = tid >> 5;
    const int lane   = tid & 31;
    const int kid    = blockIdx.x;
    const int mtile  = blockIdx.y;
    const int warp_m = wid >> 3;       // 0..1 (64 rows)
    const int warp_n = wid & 7;        // 0..7 (32 cols)

    // scan roles: one p's 4 segments live in ONE warp
    const int sp   = wid * 8 + (lane & 7);     // p in [0,128)
    const int seg  = lane >> 3;                // 0..3
    const int t0   = seg * 26;                 // segs 26/26/26/22
    const int seg_len = (seg == 3) ? 22 : 26;

    const float d   = 0.95122942450071403f;   // exp(-1/20)
    const float d26 = 0.27253179303401259f;   // exp(-26/20)
    const float d52 = 0.07427357821433388f;   // exp(-52/20)

    // ---- zero pads once ----
    for (int i = tid; i < 128 * 6; i += 512) {            // A bytes [200,224)
        int row = i / 6, off = (i % 6) * 4;
        *(uint32_t*)(smem + SM_A + row * A_ROW_B + 200 + off) = 0u;
    }
    for (int i = tid; i < 2 * 12 * 128; i += 512) {       // B rows 100..111, both
        int half = i / (12 * 128);
        int rem  = i % (12 * 128);
        int row  = 100 + rem / 128, off = (rem % 128) * 4;
        *(uint32_t*)(smem + (half ? SM_B1 : SM_B0) + row * B_ROW_B + off) = 0u;
    }
    for (int i = tid; i < 4 * STG_ROW_F; i += 512)        // staging slack rows
        stg[100 * STG_ROW_F + i] = 0.0f;

    float acc[4][4][4];
    #pragma unroll
    for (int i = 0; i < 4; ++i)
        #pragma unroll
        for (int j = 0; j < 4; ++j)
            #pragma unroll
            for (int c = 0; c < 4; ++c) acc[i][j][c] = 0.0f;

    const int nb = (BB - kid + KSPLIT - 1) / KSPLIT;   // 6 or 7 batches

    // ---- cp.async: pre[b] tile [t][p] fp32 -> staging ----
    auto issue_pre = [&](int b) {
        const float* src = pre + (size_t)b * TT * NPRE + mtile * 128;
        #pragma unroll
        for (int it = 0; it < 7; ++it) {
            int f = tid + it * 512;
            if (f < 3200) {
                int t = f >> 5, g = f & 31;
                cp_async_16(su + SM_STG + t * STG_ROW_B + g * 16,
                            src + (size_t)t * NPRE + g * 4);
            }
        }
        CP_ASYNC_COMMIT();
    };

    // ---- post chunk load / store (chunks of float4s, stride 512 threads) ----
    auto ldg_post = [&](int b, float4* v, int it0, int cnt) {
        const float4* psrc = (const float4*)(post + (size_t)b * TT * NPOST);
        #pragma unroll
        for (int k = 0; k < 5; ++k) {
            if (k < cnt) {
                int f = tid + (it0 + k) * 512;
                if (f < 6400) v[k] = psrc[f];
            }
        }
    };
    auto sts_post = [&](int buf, const float4* v, int it0, int cnt) {
        char* bbase = smem + (buf ? SM_B1 : SM_B0);
        #pragma unroll
        for (int k = 0; k < 5; ++k) {
            if (k < cnt) {
                int f = tid + (it0 + k) * 512;
                if (f < 6400) {
                    int t = f >> 6, qg = f & 63;
                    *(uint2*)(bbase + t * B_ROW_B + qg * 8) =
                        make_uint2(pack_bf16x2(v[k].x, v[k].y), pack_bf16x2(v[k].z, v[k].w));
                }
            }
        }
    };

    // ---- scan(b): shuffle-carry trace recurrence staging -> A (no LDG) ----
    auto scan = [&](int b) {
        (void)b;
        float xr[26];
        #pragma unroll
        for (int i = 0; i < 26; ++i)
            xr[i] = stg[(t0 + i) * STG_ROW_F + sp];

        float L = 0.0f;
        #pragma unroll
        for (int i = 0; i < 26; ++i)
            L = d * (L + xr[i]);

        float y = L;
        float s1 = __shfl_up_sync(0xffffffffu, y, 8);
        if (seg >= 1) y += d26 * s1;
        float s2 = __shfl_up_sync(0xffffffffu, y, 16);
        if (seg >= 2) y += d52 * s2;
        float Cin = __shfl_up_sync(0xffffffffu, y, 8);
        float C = (seg >= 1) ? Cin : 0.0f;

        char* arow = smem + SM_A + sp * A_ROW_B + t0 * 2;
        #pragma unroll
        for (int i = 0; i < 26; i += 2) {
            if (i < seg_len) {
                float c0 = C;
                C = d * (C + xr[i]);
                float c1 = C;
                C = d * (C + xr[i + 1]);
                *(uint32_t*)(arow + i * 2) = pack_bf16x2(c0, c1);
            }
        }
    };

    // ---- prologue: batch 0 tiles (serial) ----
    issue_pre(kid);
    CP_ASYNC_WAIT0();
    __syncthreads();          // pads + staging(0) ready
    {
        float4 v[5];
        ldg_post(kid, v, 0, 5);  sts_post(0, v, 0, 5);
        ldg_post(kid, v, 5, 4);  sts_post(0, v, 5, 4);
        ldg_post(kid, v, 9, 4);  sts_post(0, v, 9, 4);
        scan(kid);
    }
    __syncthreads();

    // ldmatrix lane addressing
    const int a_row  = (lane & 15);
    const int a_colh = (lane >> 4) * 8;
    const int bg  = lane >> 3;
    const int bl8 = lane & 7;
    const int b_krow = (bg & 1) * 8 + bl8;
    const int b_qoff = (bg >> 1) * 8;

    const uint32_t A = su + SM_A;

    // one ks-step of MMA
    auto mma_step = [&](uint32_t Bb, int ks) {
        uint32_t afrag[4][4];
        uint32_t bfrag[4][2];
        #pragma unroll
        for (int mi = 0; mi < 4; ++mi) {
            uint32_t addr = A + (uint32_t)((warp_m * 64 + mi * 16 + a_row) * A_ROW_B
                                           + (a_colh + ks * 16) * 2);
            ldmatrix_x4(afrag[mi], addr);
        }
        #pragma unroll
        for (int nip = 0; nip < 2; ++nip) {
            uint32_t addr = Bb + (uint32_t)((ks * 16 + b_krow) * B_ROW_B
                                            + (warp_n * 32 + nip * 16 + b_qoff) * 2);
            uint32_t r[4];
            ldmatrix_x4_trans(r, addr);
            bfrag[nip * 2 + 0][0] = r[0]; bfrag[nip * 2 + 0][1] = r[1];
            bfrag[nip * 2 + 1][0] = r[2]; bfrag[nip * 2 + 1][1] = r[3];
        }
        #pragma unroll
        for (int mi = 0; mi < 4; ++mi)
            #pragma unroll
            for (int ni = 0; ni < 4; ++ni)
                mma_16816(acc[mi][ni], afrag[mi], bfrag[ni]);
    };

    for (int j = 0; j < nb; ++j) {
        const int buf = j & 1;
        const uint32_t Bb = su + (buf ? SM_B1 : SM_B0);
        const bool more = (j + 1 < nb);
        const int bnext = kid + (j + 1) * KSPLIT;

        if (more) issue_pre(bnext);       // staging(j+1) DMA overlaps MMA(j)

        // ---- MMA with post-convert chunks interleaved (fills B[buf^1]) ----
        float4 v[5];
        if (more) ldg_post(bnext, v, 0, 5);
        mma_step(Bb, 0);
        mma_step(Bb, 1);
        if (more) { sts_post(buf ^ 1, v, 0, 5); ldg_post(bnext, v, 5, 4); }
        mma_step(Bb, 2);
        mma_step(Bb, 3);
        if (more) { sts_post(buf ^ 1, v, 5, 4); ldg_post(bnext, v, 9, 4); }
        mma_step(Bb, 4);
        mma_step(Bb, 5);
        if (more) sts_post(buf ^ 1, v, 9, 4);
        mma_step(Bb, 6);

        // ---- only the scan remains exposed ----
        if (more) {
            CP_ASYNC_WAIT0();      // staging(j+1) landed
            __syncthreads();       // all warps done reading A of batch j
            scan(bnext);           // A overwrite (LDS+FFMA+shfl only)
            __syncthreads();       // A(j+1) + B(buf^1) visible
        }
    }

    // ---- epilogue: scale + RED atomics straight into d_out ----
    const float scale = (0.005f - 0.00525f) / (float)KTOT;
    const int p_base = mtile * 128 + warp_m * 64;
    const int q_base = warp_n * 32;
    #pragma unroll
    for (int mi = 0; mi < 4; ++mi) {
        #pragma unroll
        for (int ni = 0; ni < 4; ++ni) {
            int p0 = p_base + mi * 16 + (lane >> 2);
            int q  = q_base + ni * 8 + (lane & 3) * 2;
            float* o0 = out + (size_t)p0 * NPOST + q;
            float* o1 = out + (size_t)(p0 + 8) * NPOST + q;
            atomicAdd(o0,     acc[mi][ni][0] * scale);
            atomicAdd(o0 + 1, acc[mi][ni][1] * scale);
            atomicAdd(o1,     acc[mi][ni][2] * scale);
            atomicAdd(o1 + 1, acc[mi][ni][3] * scale);
        }
    }
}

// ============================================================================
// Launch
// ============================================================================
extern "C" void kernel_launch(void* const* d_in, const int* in_sizes, int n_in,
                              void* d_out, int out_size) {
    (void)in_sizes; (void)n_in; (void)out_size;
    const float* pre  = (const float*)d_in[0];
    const float* post = (const float*)d_in[1];
    float* out = (float*)d_out;

    cudaFuncSetAttribute(stdp_fused_kernel,
                         cudaFuncAttributeMaxDynamicSharedMemorySize, GEMM_SMEM);

    stdp_zero_kernel<<<64, 256>>>((float4*)out);   // 65536 floats
    stdp_fused_kernel<<<dim3(KSPLIT, 2), 512, GEMM_SMEM>>>(pre, post, out);
}

// round 14
// speedup vs baseline: 1.0448x; 1.0448x over previous
#include <cuda_runtime.h>
#include <cuda_fp16.h>
#include <cstdint>

// ============================================================================
// Problem constants
// ============================================================================
#define BB       512
#define TT       100          // K per batch
#define TPAD     112          // padded to 7 x k16
#define NPRE     256
#define NPOST    256
#define KTOT     (BB * TT)    // 51200
#define KSPLIT   74           // grid (74, 2 mtiles) = 148 CTAs = one wave

// A tile (trace fp16, [p][t]): 128 rows, stride 240B
#define A_ROW_B   240
#define A_TILE_B  (128 * A_ROW_B)       // 30720
// B tile (post fp16, [t][q]): 112 rows x 256 fp16, stride 528B
#define B_ROW_B   528
#define B_TILE_B  (TPAD * B_ROW_B)      // 59136
// pre staging (fp32, [t][p]): 104 rows (4 zeroed slack) x 132 f32
#define STG_ROW_B 528
#define STG_ROW_F 132
#define STG_B     (104 * STG_ROW_B)     // 54912

#define SM_A      0
#define SM_B      A_TILE_B                         // 30720
#define SM_STG    (A_TILE_B + B_TILE_B)            // 89856
#define GEMM_SMEM (SM_STG + STG_B)                 // 144768

// ============================================================================
// PTX helpers (baseline PTX only — tcgen05 unavailable on plain sm_103 target)
// ============================================================================
__device__ __forceinline__ void ldmatrix_x4(uint32_t* r, uint32_t addr) {
    asm volatile("ldmatrix.sync.aligned.m8n8.x4.shared.b16 {%0,%1,%2,%3}, [%4];"
                 : "=r"(r[0]), "=r"(r[1]), "=r"(r[2]), "=r"(r[3]) : "r"(addr));
}
__device__ __forceinline__ void ldmatrix_x4_trans(uint32_t* r, uint32_t addr) {
    asm volatile("ldmatrix.sync.aligned.m8n8.x4.trans.shared.b16 {%0,%1,%2,%3}, [%4];"
                 : "=r"(r[0]), "=r"(r[1]), "=r"(r[2]), "=r"(r[3]) : "r"(addr));
}
// fp16-accumulator MMA: D(f16x2 x2) = A(f16) * B(f16) + C(f16x2 x2)
__device__ __forceinline__ void mma_16816_f16(uint32_t* c, const uint32_t* a, const uint32_t* b) {
    asm volatile(
        "mma.sync.aligned.m16n8k16.row.col.f16.f16.f16.f16 "
        "{%0,%1}, {%2,%3,%4,%5}, {%6,%7}, {%0,%1};"
        : "+r"(c[0]), "+r"(c[1])
        : "r"(a[0]), "r"(a[1]), "r"(a[2]), "r"(a[3]), "r"(b[0]), "r"(b[1]));
}
__device__ __forceinline__ uint32_t smem_to_u32(const void* smem_ptr) {
    uint32_t addr;
    asm("{ .reg .u64 tmp; cvta.to.shared.u64 tmp, %1; cvt.u32.u64 %0, tmp; }"
        : "=r"(addr) : "l"(smem_ptr));
    return addr;
}
__device__ __forceinline__ void cp_async_16(uint32_t dst_smem, const void* src) {
    asm volatile("cp.async.cg.shared.global [%0], [%1], 16;"
                 :: "r"(dst_smem), "l"(src) : "memory");
}
#define CP_ASYNC_COMMIT() asm volatile("cp.async.commit_group;" ::: "memory")
#define CP_ASYNC_WAIT0()  asm volatile("cp.async.wait_group 0;" ::: "memory")

__device__ __forceinline__ uint32_t pack_f16x2(float a, float b) {
    __half2 h = __floats2half2_rn(a, b);   // .x = a (low), .y = b (high)
    return *(uint32_t*)&h;
}

// ============================================================================
// Kernel 0: zero the output (d_out is poisoned; atomics need a clean base)
// ============================================================================
__global__ void stdp_zero_kernel(float4* __restrict__ out) {
    out[blockIdx.x * blockDim.x + threadIdx.x] = make_float4(0.f, 0.f, 0.f, 0.f);
}

// ============================================================================
// Fused kernel: cp.async pre staging + shuffle-carry trace scan + latency-
//   hidden post convert + fp16-accum HMMA GEMM.
//   grid (74, mtile 2) = 148 CTAs, 512 threads = 16 warps (2 M x 8 N)
// ============================================================================
__global__ void __launch_bounds__(512, 1) stdp_fused_kernel(
    const float* __restrict__ pre, const float* __restrict__ post,
    float* __restrict__ out)
{
    extern __shared__ __align__(16) char smem[];
    const uint32_t su = smem_to_u32(smem);
    float* stg = (float*)(smem + SM_STG);      // [104][132] fp32 pre staging

    const int tid    = threadIdx.x;
    const int wid    = tid >> 5;
    const int lane   = tid & 31;
    const int kid    = blockIdx.x;
    const int mtile  = blockIdx.y;
    const int warp_m = wid >> 3;       // 0..1 (64 rows)
    const int warp_n = wid & 7;        // 0..7 (32 cols)

    // scan roles: one p's 4 segments live in ONE warp
    const int sp   = wid * 8 + (lane & 7);     // p in [0,128)
    const int seg  = lane >> 3;                // 0..3
    const int t0   = seg * 26;                 // segs 26/26/26/22
    const int seg_len = (seg == 3) ? 22 : 26;

    const float d   = 0.95122942450071403f;   // exp(-1/20)
    const float d26 = 0.27253179303401259f;   // exp(-26/20)
    const float d52 = 0.07427357821433388f;   // exp(-52/20)

    // ---- zero pads once (prepare only writes t < 100) ----
    for (int i = tid; i < 128 * 6; i += 512) {            // A bytes [200,224)
        int row = i / 6, off = (i % 6) * 4;
        *(uint32_t*)(smem + SM_A + row * A_ROW_B + 200 + off) = 0u;
    }
    for (int i = tid; i < 12 * 128; i += 512) {           // B rows 100..111
        int row = 100 + i / 128, off = (i % 128) * 4;
        *(uint32_t*)(smem + SM_B + row * B_ROW_B + off) = 0u;
    }
    for (int i = tid; i < 4 * STG_ROW_F; i += 512)        // staging slack rows
        stg[100 * STG_ROW_F + i] = 0.0f;

    // fp16x2 accumulators: [mi][ni][2] (c0: rows lane/4, c1: rows +8)
    uint32_t acc[4][4][2];
    #pragma unroll
    for (int i = 0; i < 4; ++i)
        #pragma unroll
        for (int j = 0; j < 4; ++j) {
            acc[i][j][0] = 0u; acc[i][j][1] = 0u;
        }

    const int nb = (BB - kid + KSPLIT - 1) / KSPLIT;   // 6 or 7 batches

    // ---- issue cp.async: pre[b] tile [t][p] fp32 -> staging ----
    auto issue_pre = [&](int b) {
        const float* src = pre + (size_t)b * TT * NPRE + mtile * 128;
        #pragma unroll
        for (int it = 0; it < 7; ++it) {
            int f = tid + it * 512;
            if (f < 3200) {                     // 100 rows x 32 chunks of 16B
                int t = f >> 5, g = f & 31;
                cp_async_16(su + SM_STG + t * STG_ROW_B + g * 16,
                            src + (size_t)t * NPRE + g * 4);
            }
        }
        CP_ASYNC_COMMIT();
    };

    // ---- prepare(b): shuffle-carry scan + latency-hidden post convert ----
    auto prepare = [&](int b) {
        const float4* psrc = (const float4*)(post + (size_t)b * TT * NPOST);

        // LDS this thread's 26 pre values (bank-conflict-free, stride 132)
        float xr[26];
        #pragma unroll
        for (int i = 0; i < 26; ++i)
            xr[i] = stg[(t0 + i) * STG_ROW_F + sp];

        // post LDG half 1 (6 x float4); latency hides behind phase-1 chain
        float4 v0[6];
        #pragma unroll
        for (int it = 0; it < 6; ++it)
            v0[it] = psrc[tid + it * 512];       // f < 3072

        // phase 1: local decayed sum (register chain)
        float L = 0.0f;
        #pragma unroll
        for (int i = 0; i < 26; ++i)
            L = d * (L + xr[i]);

        // weighted Kogge-Stone across segments (in-warp, stride 8 lanes)
        float y = L;
        float s1 = __shfl_up_sync(0xffffffffu, y, 8);
        if (seg >= 1) y += d26 * s1;
        float s2 = __shfl_up_sync(0xffffffffu, y, 16);
        if (seg >= 2) y += d52 * s2;
        float Cin = __shfl_up_sync(0xffffffffu, y, 8);
        float C = (seg >= 1) ? Cin : 0.0f;       // carry before this segment

        // STS post half 1 (fp16)
        #pragma unroll
        for (int it = 0; it < 6; ++it) {
            int f = tid + it * 512;
            int t = f >> 6, qg = f & 63;
            *(uint2*)(smem + SM_B + t * B_ROW_B + qg * 8) =
                make_uint2(pack_f16x2(v0[it].x, v0[it].y), pack_f16x2(v0[it].z, v0[it].w));
        }

        // post LDG half 2 (7 x float4, guarded); hides behind phase-2 chain
        float4 v1[7];
        #pragma unroll
        for (int it = 0; it < 7; ++it) {
            int f = tid + (6 + it) * 512;        // 3072 .. 6655
            if (f < 6400) v1[it] = psrc[f];
        }

        // phase 2: emit trace[t] = carry-before-t, packed fp16x2 STS.32
        char* arow = smem + SM_A + sp * A_ROW_B + t0 * 2;   // 4-aligned
        #pragma unroll
        for (int i = 0; i < 26; i += 2) {
            if (i < seg_len) {
                float c0 = C;
                C = d * (C + xr[i]);
                float c1 = C;
                C = d * (C + xr[i + 1]);
                *(uint32_t*)(arow + i * 2) = pack_f16x2(c0, c1);
            }
        }

        // STS post half 2 (fp16)
        #pragma unroll
        for (int it = 0; it < 7; ++it) {
            int f = tid + (6 + it) * 512;
            if (f < 6400) {
                int t = f >> 6, qg = f & 63;
                *(uint2*)(smem + SM_B + t * B_ROW_B + qg * 8) =
                    make_uint2(pack_f16x2(v1[it].x, v1[it].y), pack_f16x2(v1[it].z, v1[it].w));
            }
        }
    };

    // ---- prologue ----
    issue_pre(kid);
    CP_ASYNC_WAIT0();
    __syncthreads();          // pads + staging(0) ready
    prepare(kid);
    __syncthreads();

    // ldmatrix lane addressing
    const int a_row  = (lane & 15);
    const int a_colh = (lane >> 4) * 8;
    const int bg  = lane >> 3;
    const int bl8 = lane & 7;
    const int b_krow = (bg & 1) * 8 + bl8;
    const int b_qoff = (bg >> 1) * 8;

    const uint32_t A  = su + SM_A;
    const uint32_t Bb = su + SM_B;

    for (int j = 0; j < nb; ++j) {
        // prefetch next batch's pre (async, overlaps MMA below)
        if (j + 1 < nb)
            issue_pre(kid + (j + 1) * KSPLIT);

        // ---- MMA over 7 k16 steps (fp16 accumulators) ----
        #pragma unroll
        for (int ks = 0; ks < 7; ++ks) {
            uint32_t afrag[4][4];
            uint32_t bfrag[4][2];
            #pragma unroll
            for (int mi = 0; mi < 4; ++mi) {
                uint32_t addr = A + (uint32_t)((warp_m * 64 + mi * 16 + a_row) * A_ROW_B
                                               + (a_colh + ks * 16) * 2);
                ldmatrix_x4(afrag[mi], addr);
            }
            #pragma unroll
            for (int nip = 0; nip < 2; ++nip) {
                uint32_t addr = Bb + (uint32_t)((ks * 16 + b_krow) * B_ROW_B
                                                + (warp_n * 32 + nip * 16 + b_qoff) * 2);
                uint32_t r[4];
                ldmatrix_x4_trans(r, addr);
                bfrag[nip * 2 + 0][0] = r[0]; bfrag[nip * 2 + 0][1] = r[1];
                bfrag[nip * 2 + 1][0] = r[2]; bfrag[nip * 2 + 1][1] = r[3];
            }
            #pragma unroll
            for (int mi = 0; mi < 4; ++mi)
                #pragma unroll
                for (int ni = 0; ni < 4; ++ni)
                    mma_16816_f16(acc[mi][ni], afrag[mi], bfrag[ni]);
        }

        // ---- build next batch's tiles ----
        if (j + 1 < nb) {
            CP_ASYNC_WAIT0();      // staging(j+1) landed
            __syncthreads();       // all warps done reading A/B of batch j
            prepare(kid + (j + 1) * KSPLIT);
            __syncthreads();       // tiles for j+1 visible
        }
    }

    // ---- epilogue: unpack fp16 acc, scale, RED atomics into d_out ----
    const float scale = (0.005f - 0.00525f) / (float)KTOT;
    const int p_base = mtile * 128 + warp_m * 64;
    const int q_base = warp_n * 32;
    #pragma unroll
    for (int mi = 0; mi < 4; ++mi) {
        #pragma unroll
        for (int ni = 0; ni < 4; ++ni) {
            int p0 = p_base + mi * 16 + (lane >> 2);
            int q  = q_base + ni * 8 + (lane & 3) * 2;
            float2 f0 = __half22float2(*(__half2*)&acc[mi][ni][0]);
            float2 f1 = __half22float2(*(__half2*)&acc[mi][ni][1]);
            float* o0 = out + (size_t)p0 * NPOST + q;
            float* o1 = out + (size_t)(p0 + 8) * NPOST + q;
            atomicAdd(o0,     f0.x * scale);
            atomicAdd(o0 + 1, f0.y * scale);
            atomicAdd(o1,     f1.x * scale);
            atomicAdd(o1 + 1, f1.y * scale);
        }
    }
}

// ============================================================================
// Launch
// ============================================================================
extern "C" void kernel_launch(void* const* d_in, const int* in_sizes, int n_in,
                              void* d_out, int out_size) {
    (void)in_sizes; (void)n_in; (void)out_size;
    const float* pre  = (const float*)d_in[0];
    const float* post = (const float*)d_in[1];
    float* out = (float*)d_out;

    cudaFuncSetAttribute(stdp_fused_kernel,
                         cudaFuncAttributeMaxDynamicSharedMemorySize, GEMM_SMEM);

    stdp_zero_kernel<<<64, 256>>>((float4*)out);   // 65536 floats
    stdp_fused_kernel<<<dim3(KSPLIT, 2), 512, GEMM_SMEM>>>(pre, post, out);
}